// round 11
// baseline (speedup 1.0000x reference)
#include <cuda_runtime.h>
#include <cuda_bf16.h>

// Retrace: per-(b,d) reverse affine scan + MSE reduction.
// Shapes: B=2048, T=512, D=16. fp32. Output: 1 fp32 scalar.
// Two-phase, time-quartered to kill wave quantization:
//  Phase 1: 4096 blocks (1024 chain-groups x 4 time-quarters of 128 steps).
//    Block = 32 chains x 8 segments of 16 steps. Per-segment affine scan
//    (q = P*x + S, MSE quadratic in x); in-block combine produces one
//    per-chain 5-tuple (A,B,D2,DP,P2) per quarter -> static scratch.
//  Phase 2: chains the 4 quarter-tuples with the true carry (target_Q[:,-1])
//    and reduces the MSE.

#define RB 2048
#define RT 512
#define RD 16
#define NSEG 8
#define SEGLEN 16
#define QSTEPS 128
#define NQ 4
#define NGRP 1024            // chain groups of 32
#define CHAINS_PER_BLK 32
#define GAMMA 0.99f

__device__ float g_scr[NQ][NGRP][5][CHAINS_PER_BLK];   // 2.62 MB

__global__ __launch_bounds__(256, 4)
void retrace_phase1(const float* __restrict__ Q,
                    const float* __restrict__ eQ,
                    const float* __restrict__ tQ,
                    const float* __restrict__ rw,
                    const float* __restrict__ tpp,
                    const float* __restrict__ bpp)
{
    const int lane = threadIdx.x & 31;       // chain within group
    const int seg  = threadIdx.x >> 5;       // segment 0..7 within quarter
    const int gq   = blockIdx.x;             // chain group 0..1023
    const int qt   = blockIdx.y;             // time quarter 0..3
    const int chain = gq * CHAINS_PER_BLK + lane;
    const int b = chain >> 4;                // D = 16
    const int d = chain & 15;

    const size_t base = (size_t)b * (RT * RD) + d;
    const float* q_p   = Q   + base;
    const float* e_p   = eQ  + base;
    const float* tq_p  = tQ  + base;
    const float* r_p   = rw  + base;
    const float* tpp_p = tpp + base;
    const float* bpp_p = bpp + (size_t)b * RT;

    const int lo = qt * QSTEPS + seg * SEGLEN;
    int hi = lo + SEGLEN - 1;
    if (hi > RT - 2) hi = RT - 2;            // last segment of last quarter: 15 steps

    // Backward scan within segment: q = P*x + S (x = carry entering at t=hi+1)
    float P = 1.0f, S = 0.0f;
    float sumD2 = 0.0f, sumDP = 0.0f, sumP2 = 0.0f;

    #pragma unroll 4
    for (int t = hi; t >= lo; --t) {
        const int j = t + 1;
        float lw  = tpp_p[j * RD] - bpp_p[j];
        float gc  = GAMMA * __expf(fminf(lw, 0.0f));
        float bse = fmaf(GAMMA, e_p[j * RD], r_p[t * RD]);
        bse       = fmaf(-gc, tq_p[j * RD], bse);
        P = gc * P;
        S = fmaf(gc, S, bse);
        float dv = q_p[t * RD] - S;          // diff = dv - P*x
        sumD2 = fmaf(dv, dv, sumD2);
        sumDP = fmaf(dv, P,  sumDP);
        sumP2 = fmaf(P,  P,  sumP2);
    }

    __shared__ float shA [NSEG][CHAINS_PER_BLK];
    __shared__ float shB [NSEG][CHAINS_PER_BLK];
    __shared__ float shD2[NSEG][CHAINS_PER_BLK];
    __shared__ float shDP[NSEG][CHAINS_PER_BLK];
    __shared__ float shP2[NSEG][CHAINS_PER_BLK];
    shA [seg][lane] = P;
    shB [seg][lane] = S;
    shD2[seg][lane] = sumD2;
    shDP[seg][lane] = sumDP;
    shP2[seg][lane] = sumP2;
    __syncthreads();

    // Warp 0 combines the 8 segments into one quarter tuple per chain.
    // Quarter carry-in x enters at segment 7 (highest t). Maintain x_s_in =
    // A*x + Bc; fold each segment's quadratic into (D2,DP,P2) in terms of x.
    if (seg == 0) {
        float A = 1.0f, Bc = 0.0f;
        float D2 = 0.0f, DP = 0.0f, P2 = 0.0f;
        #pragma unroll
        for (int s = NSEG - 1; s >= 0; --s) {
            float sP  = shA [s][lane];
            float sS  = shB [s][lane];
            float sD2 = shD2[s][lane];
            float sDP = shDP[s][lane];
            float sP2 = shP2[s][lane];
            // err_s(x_in) with x_in = A*x + Bc:
            float t1 = fmaf(-Bc, sP2, sDP);          // DP_s - Bc*P2_s
            D2 += fmaf(Bc, fmaf(Bc, sP2, -2.0f * sDP), sD2);
            DP  = fmaf(A, t1, DP);
            P2  = fmaf(A * A, sP2, P2);
            // carry through segment s: x_{s-1,in} = sP*(A*x+Bc) + sS
            A  = sP * A;
            Bc = fmaf(sP, Bc, sS);
        }
        g_scr[qt][gq][0][lane] = A;
        g_scr[qt][gq][1][lane] = Bc;
        g_scr[qt][gq][2][lane] = D2;
        g_scr[qt][gq][3][lane] = DP;
        g_scr[qt][gq][4][lane] = P2;
    }
}

// Phase 2: 128 blocks x 256 threads; warp = one chain group, lane = chain.
__global__ __launch_bounds__(256, 4)
void retrace_phase2(const float* __restrict__ tQ,
                    float* __restrict__ out)
{
    const int lane = threadIdx.x & 31;
    const int w    = threadIdx.x >> 5;               // warp in block (0..7)
    const int gq   = blockIdx.x * 8 + w;             // chain group
    const int chain = gq * CHAINS_PER_BLK + lane;
    const int b = chain >> 4;
    const int d = chain & 15;

    // initial carry = target_Q[:, -1]
    float x = tQ[(size_t)b * (RT * RD) + (size_t)(RT - 1) * RD + d];
    float acc = 0.0f;

    #pragma unroll
    for (int q = NQ - 1; q >= 0; --q) {
        float A  = g_scr[q][gq][0][lane];
        float Bc = g_scr[q][gq][1][lane];
        float D2 = g_scr[q][gq][2][lane];
        float DP = g_scr[q][gq][3][lane];
        float P2 = g_scr[q][gq][4][lane];
        acc += fmaf(x, fmaf(x, P2, -2.0f * DP), D2);
        x = fmaf(A, x, Bc);
    }

    const float inv_n = 1.0f / (float)((size_t)RB * (RT - 1) * RD);
    acc *= inv_n;

    #pragma unroll
    for (int off = 16; off > 0; off >>= 1)
        acc += __shfl_down_sync(0xFFFFFFFFu, acc, off);

    __shared__ float wsum[8];
    if (lane == 0) wsum[w] = acc;
    __syncthreads();
    if (w == 0) {
        float v = (lane < 8) ? wsum[lane] : 0.0f;
        #pragma unroll
        for (int off = 4; off > 0; off >>= 1)
            v += __shfl_down_sync(0xFFFFFFFFu, v, off);
        if (lane == 0)
            atomicAdd(out, v);
    }
}

extern "C" void kernel_launch(void* const* d_in, const int* in_sizes, int n_in,
                              void* d_out, int out_size)
{
    const float* Q   = (const float*)d_in[0];
    const float* eQ  = (const float*)d_in[1];
    const float* tQ  = (const float*)d_in[2];
    const float* rw  = (const float*)d_in[3];
    const float* tpp = (const float*)d_in[4];
    const float* bpp = (const float*)d_in[5];
    float* out = (float*)d_out;

    cudaMemsetAsync(out, 0, sizeof(float), 0);

    dim3 grid1(NGRP, NQ);                    // 1024 x 4 = 4096 blocks
    retrace_phase1<<<grid1, 256>>>(Q, eQ, tQ, rw, tpp, bpp);
    retrace_phase2<<<NGRP / 8, 256>>>(tQ, out);
}